// round 17
// baseline (speedup 1.0000x reference)
#include <cuda_runtime.h>
#include <cuda_bf16.h>

#define NB 32
#define LL 1024
#define TT 64
#define PG_WORDS (LL * 33)     // bf16x2 words, row stride 33 (33 = 1 mod 32)

#define FMA2(d,a,b,c) asm("fma.rn.f32x2 %0, %1, %2, %3;" : "=l"(d) : "l"(a), "l"(b), "l"(c))
#define MUL2(d,a,b)   asm("mul.rn.f32x2 %0, %1, %2;"     : "=l"(d) : "l"(a), "l"(b))
#define ADD2(d,a,b)   asm("add.rn.f32x2 %0, %1, %2;"     : "=l"(d) : "l"(a), "l"(b))
#define UNPACK2(lo,hi,v) asm("mov.b64 {%0,%1}, %2;" : "=f"(lo), "=f"(hi) : "l"(v))
#define PACK2(v,lo,hi)   asm("mov.b64 %0, {%1,%2};" : "=l"(v) : "f"(lo), "f"(hi))
#define CVTPACK(r, lo, hi) \
  asm("cvt.rn.satfinite.bf16x2.f32 %0, %1, %2;" : "=r"(r) : "f"(hi), "f"(lo))
#define MULBF2(d, a, bb) \
  asm("mul.bf16x2 %0, %1, %2;" : "=r"(d) : "r"(a), "r"(bb))
#define MMA16816(d0,d1,d2,d3,a0,a1,a2,a3,bb0,bb1) \
  asm volatile("mma.sync.aligned.m16n8k16.row.col.f32.bf16.bf16.f32 " \
      "{%0,%1,%2,%3}, {%4,%5,%6,%7}, {%8,%9}, {%0,%1,%2,%3};" \
      : "+f"(d0), "+f"(d1), "+f"(d2), "+f"(d3) \
      : "r"(a0), "r"(a1), "r"(a2), "r"(a3), "r"(bb0), "r"(bb1))
#define ONEBF2 0x3F803F80u

// Segmentation: R covers t=1..38; 22 rank-1 segments of 43 (39..984);
// W exact covers 985..1023. Cut j (j=0..22): B(j) = 38 + 43*j.
__device__ __forceinline__ int Bcut(int j) { return 38 + 43 * j; }

__global__ __launch_bounds__(128)
void crf_mma_kernel(const float* __restrict__ logits,     // [B,L,T]
                    const float* __restrict__ trans,      // [T,T]
                    const float* __restrict__ start_s,    // [T]
                    const float* __restrict__ end_s,      // [T]
                    const int* __restrict__ mask,         // [B,L] bool as int32
                    float* __restrict__ out)              // [B]
{
    extern __shared__ unsigned pgw[];    // exp(logits) bf16x2, stride-33 rows

    const int b    = blockIdx.x;         // one CTA per batch
    const int tid  = threadIdx.x;
    const int w    = tid >> 5;           // warps 0,1 fwd; 2,3 bwd
    const int lane = tid & 31;
    const int grp  = lane >> 2;          // 0..7
    const int qd   = lane & 3;           // 0..3

    // s_vec rows: 0=R, 1..22=Q_1..Q_22, 23..31 junk,
    //             32..53=P_1..P_22, 54=W, 55..63 junk
    __shared__ float s_vec[64][TT];
    __shared__ __align__(16) float xs[2][TT];   // generic fallback buffer
    __shared__ int s_red[4];
    __shared__ int s_end;

    // ---- end_idx = count(mask != 0) - 1 ; mask stored as int32 ----
    {
        const int4* mb = reinterpret_cast<const int4*>(mask + (size_t)b * LL);
        int4 m0 = mb[tid * 2], m1 = mb[tid * 2 + 1];
        int cnt = (m0.x != 0) + (m0.y != 0) + (m0.z != 0) + (m0.w != 0)
                + (m1.x != 0) + (m1.y != 0) + (m1.z != 0) + (m1.w != 0);
        #pragma unroll
        for (int o = 16; o > 0; o >>= 1) cnt += __shfl_xor_sync(~0u, cnt, o);
        if (lane == 0) s_red[w] = cnt;
        __syncthreads();
        if (tid == 0) s_end = s_red[0] + s_red[1] + s_red[2] + s_red[3] - 1;
        __syncthreads();
    }
    const int endi = s_end;
    const float* lgB = logits + (size_t)b * LL * TT;

    if (endi != 1023) {
        // ==== generic fallback (proven R11 path), duplicated across halves ====
        const int sid = tid & 63;
        unsigned long long e2[32];
        #pragma unroll
        for (int p = 0; p < 32; ++p) {
            float lo = __expf(__ldg(&trans[(2 * p)     * TT + sid]));
            float hi = __expf(__ldg(&trans[(2 * p + 1) * TT + sid]));
            PACK2(e2[p], lo, hi);
        }
        const float* lg = lgB + sid;
        int buf = 0;
        auto dot = [&]() -> float {
            const ulonglong2* bp = reinterpret_cast<const ulonglong2*>(xs[buf]);
            unsigned long long A0, A1, A2, A3;
            {
                ulonglong2 v = bp[0], u = bp[1];
                MUL2(A0, v.x, e2[0]); MUL2(A1, v.y, e2[1]);
                MUL2(A2, u.x, e2[2]); MUL2(A3, u.y, e2[3]);
            }
            #pragma unroll
            for (int qq = 1; qq < 8; ++qq) {
                ulonglong2 v = bp[2 * qq], u = bp[2 * qq + 1];
                FMA2(A0, v.x, e2[4 * qq],     A0);
                FMA2(A1, v.y, e2[4 * qq + 1], A1);
                FMA2(A2, u.x, e2[4 * qq + 2], A2);
                FMA2(A3, u.y, e2[4 * qq + 3], A3);
            }
            ADD2(A0, A0, A1); ADD2(A2, A2, A3); ADD2(A0, A0, A2);
            float lo, hi;
            UNPACK2(lo, hi, A0);
            return lo + hi;
        };
        xs[0][sid] = __expf(lg[0] + __ldg(&start_s[sid]) +
                            ((endi == 0) ? __ldg(&end_s[sid]) : 0.f));
        __syncthreads();
        int exoff = 0;
        #pragma unroll 1
        for (int t = 1; t <= endi; ++t) {
            float bb = xs[buf][0];
            int   ex = ((__float_as_int(bb) >> 23) & 255) - 127;
            float scale = __int_as_float((127 - ex) << 23);
            float g = lg[(size_t)t * TT] +
                      ((t == endi) ? __ldg(&end_s[sid]) : 0.f);
            float d = dot();
            xs[buf ^ 1][sid] = d * (scale * __expf(g));
            exoff += ex;
            buf ^= 1;
            __syncthreads();
        }
        float s = xs[buf][sid];
        #pragma unroll
        for (int o = 16; o > 0; o >>= 1) s += __shfl_xor_sync(~0u, s, o);
        if (lane == 0) reinterpret_cast<float*>(s_red)[w] = s;
        __syncthreads();
        if (tid == 0) {
            float tot = reinterpret_cast<float*>(s_red)[0] +
                        reinterpret_cast<float*>(s_red)[1];
            out[b] = __int2float_rn(exoff) * 0.693147180559945f + __logf(tot);
        }
        return;
    }

    // ---- prologue: pgw[t*33+wd] = bf16x2(exp(logits[t][2wd..2wd+1])) ----
    {
        const int ts = w;                // 0..3
        const int wd = lane;
        const float2* lg2 = reinterpret_cast<const float2*>(lgB);
        #pragma unroll 4
        for (int i = 0; i < 128; ++i) {
            int t0 = i * 8 + ts;
            int t1 = t0 + 4;
            float2 f0 = lg2[t0 * 32 + wd];
            float2 f1 = lg2[t1 * 32 + wd];
            unsigned r0, r1;
            CVTPACK(r0, __expf(f0.x), __expf(f0.y));
            CVTPACK(r1, __expf(f1.x), __expf(f1.y));
            pgw[t0 * 33 + wd] = r0;
            pgw[t1 * 33 + wd] = r1;
        }
    }
    __syncthreads();

    {
        const float esc = 0.0078125f;    // fold 2^-7 into E'
        const bool fwd = (w < 2);

        // B fragments: fwd B[k][n]=E'[k][n]; bwd B[k][n]=E'[n][k]
        unsigned int Bf[4][8][2];
        #pragma unroll
        for (int kt = 0; kt < 4; ++kt) {
            #pragma unroll
            for (int nt = 0; nt < 8; ++nt) {
                int n  = 8 * nt + grp;
                int k0 = 16 * kt + 2 * qd;
                float e00, e01, e10, e11;
                if (fwd) {
                    e00 = __expf(__ldg(&trans[(k0    ) * TT + n])) * esc;
                    e01 = __expf(__ldg(&trans[(k0 + 1) * TT + n])) * esc;
                    e10 = __expf(__ldg(&trans[(k0 + 8) * TT + n])) * esc;
                    e11 = __expf(__ldg(&trans[(k0 + 9) * TT + n])) * esc;
                } else {
                    e00 = __expf(__ldg(&trans[n * TT + k0    ])) * esc;
                    e01 = __expf(__ldg(&trans[n * TT + k0 + 1])) * esc;
                    e10 = __expf(__ldg(&trans[n * TT + k0 + 8])) * esc;
                    e11 = __expf(__ldg(&trans[n * TT + k0 + 9])) * esc;
                }
                CVTPACK(Bf[kt][nt][0], e00, e01);
                CVTPACK(Bf[kt][nt][1], e10, e11);
            }
        }

        // per-row bases and ends
        // w0: row grp: 0=R(base 0,end 38), 1..7=Q_1..7(base B(grp-1));
        //     row grp+8: Q_8..15 (base B(grp+7)); Q end = 43
        // w1: rows 0..6 = Q_16..22 (base B(15+grp)); rest junk base 0
        // w2: rows 0..15 = P_1..16 (base B(grp+1) / B(grp+9)); end 43
        // w3: rows 0..5 = P_17..22 (base B(17+grp)); row 6 = W (base 1023,
        //     epi m=39); rest junk base 984
        int base_a, base_b;
        if (w == 0) {
            base_a = (grp == 0) ? 0 : Bcut(grp - 1);
            base_b = Bcut(grp + 7);
        } else if (w == 1) {
            base_a = (grp <= 6) ? Bcut(15 + grp) : 0;
            base_b = 0;
        } else if (w == 2) {
            base_a = Bcut(grp + 1);
            base_b = Bcut(grp + 9);
        } else {
            base_a = (grp <= 5) ? Bcut(17 + grp) : ((grp == 6) ? 1023 : 984);
            base_b = 984;
        }

        // initial chain vectors -> A fragments
        auto xinit = [&](int base, bool isR, bool isW, int col) -> float {
            if (fwd) {
                if (isR) return __expf(lgB[col] + __ldg(&start_s[col]));
                return 1.0f;
            }
            float g = lgB[(size_t)base * TT + col];
            if (isW) g += __ldg(&end_s[col]);
            return __expf(g);
        };
        const bool isRa = (w == 0 && grp == 0);
        const bool isWa = (w == 3 && grp == 6);
        unsigned int Af[4][4];
        #pragma unroll
        for (int kt = 0; kt < 4; ++kt) {
            int c0 = 16 * kt + 2 * qd;
            CVTPACK(Af[kt][0], xinit(base_a, isRa, isWa, c0),
                               xinit(base_a, isRa, isWa, c0 + 1));
            CVTPACK(Af[kt][1], xinit(base_b, false, false, c0),
                               xinit(base_b, false, false, c0 + 1));
            CVTPACK(Af[kt][2], xinit(base_a, isRa, isWa, c0 + 8),
                               xinit(base_a, isRa, isWa, c0 + 9));
            CVTPACK(Af[kt][3], xinit(base_b, false, false, c0 + 8),
                               xinit(base_b, false, false, c0 + 9));
        }

        const int sgn = fwd ? 1 : -1;
        const int rowA = 16 * w + grp;       // global s_vec row ids
        const int rowB = 16 * w + grp + 8;

        #pragma unroll 1
        for (int m = 1; m <= 43; ++m) {
            const int tA = base_a + sgn * m;   // in [0, 1023] for all rows
            const int tB = base_b + sgn * m;
            unsigned ga[8], gb[8];
            #pragma unroll
            for (int nt = 0; nt < 8; ++nt) {
                ga[nt] = pgw[tA * 33 + 4 * nt + qd];
                gb[nt] = pgw[tB * 33 + 4 * nt + qd];
            }
            if (!fwd && m == 43) {            // bwd epilogue: eg = 1
                #pragma unroll
                for (int nt = 0; nt < 8; ++nt) { ga[nt] = ONEBF2; gb[nt] = ONEBF2; }
            }
            if (isWa && m == 39) {            // W epilogue: eg = 1 (row a only)
                #pragma unroll
                for (int nt = 0; nt < 8; ++nt) ga[nt] = ONEBF2;
            }

            // Y = X * E' with 2-deep mma chains (kt 0,1 -> c; kt 2,3 -> c2)
            float c[8][4], c2[8][4];
            #pragma unroll
            for (int nt = 0; nt < 8; ++nt) {
                c[nt][0]=c[nt][1]=c[nt][2]=c[nt][3]=0.f;
                c2[nt][0]=c2[nt][1]=c2[nt][2]=c2[nt][3]=0.f;
                MMA16816(c[nt][0],c[nt][1],c[nt][2],c[nt][3],
                         Af[0][0],Af[0][1],Af[0][2],Af[0][3],
                         Bf[0][nt][0],Bf[0][nt][1]);
                MMA16816(c2[nt][0],c2[nt][1],c2[nt][2],c2[nt][3],
                         Af[2][0],Af[2][1],Af[2][2],Af[2][3],
                         Bf[2][nt][0],Bf[2][nt][1]);
                MMA16816(c[nt][0],c[nt][1],c[nt][2],c[nt][3],
                         Af[1][0],Af[1][1],Af[1][2],Af[1][3],
                         Bf[1][nt][0],Bf[1][nt][1]);
                MMA16816(c2[nt][0],c2[nt][1],c2[nt][2],c2[nt][3],
                         Af[3][0],Af[3][1],Af[3][2],Af[3][3],
                         Bf[3][nt][0],Bf[3][nt][1]);
            }

            #pragma unroll
            for (int nt = 0; nt < 8; ++nt) {
                float y0 = c[nt][0] + c2[nt][0];
                float y1 = c[nt][1] + c2[nt][1];
                float y2 = c[nt][2] + c2[nt][2];
                float y3 = c[nt][3] + c2[nt][3];
                unsigned Pa, Pb;
                CVTPACK(Pa, y0, y1);
                CVTPACK(Pb, y2, y3);
                MULBF2(Pa, Pa, ga[nt]);
                MULBF2(Pb, Pb, gb[nt]);

                int colb = 8 * nt + 2 * qd;
                // per-row snapshots
                if (isRa && m == 38) {          // R ends at step 38
                    __nv_bfloat162 v = *reinterpret_cast<__nv_bfloat162*>(&Pa);
                    s_vec[0][colb]     = __bfloat162float(v.x);
                    s_vec[0][colb + 1] = __bfloat162float(v.y);
                }
                if (isWa && m == 39) {          // W ends at step 39
                    __nv_bfloat162 v = *reinterpret_cast<__nv_bfloat162*>(&Pa);
                    s_vec[54][colb]     = __bfloat162float(v.x);
                    s_vec[54][colb + 1] = __bfloat162float(v.y);
                }
                if (m == 43) {
                    __nv_bfloat162 va_ = *reinterpret_cast<__nv_bfloat162*>(&Pa);
                    __nv_bfloat162 vb_ = *reinterpret_cast<__nv_bfloat162*>(&Pb);
                    if (!isRa && !isWa) {
                        s_vec[rowA][colb]     = __bfloat162float(va_.x);
                        s_vec[rowA][colb + 1] = __bfloat162float(va_.y);
                    }
                    s_vec[rowB][colb]     = __bfloat162float(vb_.x);
                    s_vec[rowB][colb + 1] = __bfloat162float(vb_.y);
                }

                int kt = nt >> 1;
                if ((nt & 1) == 0) { Af[kt][0] = Pa; Af[kt][1] = Pb; }
                else               { Af[kt][2] = Pa; Af[kt][3] = Pb; }
            }
        }
    }

    __syncthreads();

    // ============ in-CTA telescoped rank-1 combine (warp 0) ============
    // rows: x_0 = R = row 0; Q_j = row j; P_j = row 31+j; W = row 54
    // logZ = sum_{j=1}^{22}[log(P_j . x_{j-1}) - log Sum Q_j] + log(W . Q_22)
    //        + ln2 * 7 * 1023
    if (tid < 32) {
        const int l = tid;
        float acc = 0.0f;
        #pragma unroll 1
        for (int j = 1; j <= 22; ++j) {
            float d = s_vec[31 + j][l] * s_vec[j - 1][l]
                    + s_vec[31 + j][l + 32] * s_vec[j - 1][l + 32];
            float s = s_vec[j][l] + s_vec[j][l + 32];
            #pragma unroll
            for (int o = 16; o > 0; o >>= 1) {
                d += __shfl_xor_sync(~0u, d, o);
                s += __shfl_xor_sync(~0u, s, o);
            }
            acc += __logf(d) - __logf(s);
        }
        {
            float d = s_vec[54][l] * s_vec[22][l]
                    + s_vec[54][l + 32] * s_vec[22][l + 32];
            #pragma unroll
            for (int o = 16; o > 0; o >>= 1) d += __shfl_xor_sync(~0u, d, o);
            acc += __logf(d);
        }
        if (l == 0)
            out[b] = acc + 7161.0f * 0.693147180559945f;   // 7*1023*ln2
    }
}

extern "C" void kernel_launch(void* const* d_in, const int* in_sizes, int n_in,
                              void* d_out, int out_size) {
    const float* logits        = (const float*)d_in[0];
    const float* transitions   = (const float*)d_in[1];
    const float* start_states  = (const float*)d_in[2];
    const float* end_states    = (const float*)d_in[3];
    const int*   mask          = (const int*)d_in[4];
    float* out = (float*)d_out;
    (void)in_sizes; (void)n_in; (void)out_size;

    cudaFuncSetAttribute(crf_mma_kernel,
                         cudaFuncAttributeMaxDynamicSharedMemorySize,
                         PG_WORDS * 4);
    crf_mma_kernel<<<NB, 128, PG_WORDS * 4>>>(logits, transitions, start_states,
                                              end_states, mask, out);
}